// round 12
// baseline (speedup 1.0000x reference)
#include <cuda_runtime.h>
#include <cuda_bf16.h>
#include <math.h>

#define NN 4096
#define EE 131072
#define DD 512
#define HHH 512
#define OUTC 64
#define NWRD 128   // 4096 bits / 32
#define KT 32
#define BSTRIDE 40        // smem row stride in halves (80B = 16B-aligned rows)
#define TSH (128 * BSTRIDE)

// ---------------- scratch (device globals; no allocations) ----------------
__device__ unsigned g_Abits[NN * NWRD];
__device__ unsigned g_Rbits[NN * NWRD];
__device__ float g_cinv[NN];
__device__ int g_src[EE], g_dst[EE];
__device__ int g_deg_src[NN], g_deg_dst[NN];
__device__ int g_off_src[NN + 1], g_off_dst[NN + 1];
__device__ int g_cur_src[NN], g_cur_dst[NN];
__device__ int g_csr_src[EE], g_csr_dst[EE];
__device__ float g_inv[NN];
__device__ float g_cose[EE];
__device__ float g_ego[NN * DD], g_cut[NN * DD], g_cosf[NN * DD];
__device__ float g_logits[NN * OUTC];
// tensor-core buffers (bf16 hi/lo splits)
__device__ __nv_bfloat16 g_Rb16[(size_t)NN * NN];   // 32 MB, R as exact 0/1 bf16
__device__ __nv_bfloat16 g_xt_hi[(size_t)DD * NN];  // x^T hi split [feature][node]
__device__ __nv_bfloat16 g_xt_lo[(size_t)DD * NN];
__device__ __nv_bfloat16 g_xh[NN * DD], g_xl[NN * DD];          // x row-major split
__device__ __nv_bfloat16 g_aggEh[NN * DD], g_aggEl[NN * DD];
__device__ __nv_bfloat16 g_aggCh[NN * DD], g_aggCl[NN * DD];
__device__ __nv_bfloat16 g_aggSh[NN * DD], g_aggSl[NN * DD];
__device__ __nv_bfloat16 g_combh[(size_t)NN * 4 * HHH], g_combl[(size_t)NN * 4 * HHH];
// transposed+split weights: 4 encoder weights [HHH][DD] then fc [OUTC][4*HHH]
#define WT_FC_OFF (4 * DD * HHH)
__device__ __nv_bfloat16 g_Wth[4 * DD * HHH + OUTC * 4 * HHH];
__device__ __nv_bfloat16 g_Wtl[4 * DD * HHH + OUTC * 4 * HHH];

// ---------------- setup kernels ----------------

__global__ void k_zero() {
    int idx = blockIdx.x * blockDim.x + threadIdx.x;
    for (int i = idx; i < NN * NWRD; i += gridDim.x * blockDim.x) g_Abits[i] = 0u;
    if (idx < NN) {
        g_deg_src[idx] = 0; g_deg_dst[idx] = 0;
        g_cur_src[idx] = 0; g_cur_dst[idx] = 0;
    }
}

// convert edge_index, with per-block int64/int32 detection (odd words of the
// first 256 entries all zero => int64)
__global__ void k_convert(const unsigned* __restrict__ raw) {
    __shared__ unsigned red[256];
    int t = threadIdx.x;
    red[t] = raw[2 * t + 1];
    __syncthreads();
    for (int d = 128; d > 0; d >>= 1) {
        if (t < d) red[t] |= red[t + d];
        __syncthreads();
    }
    int is64 = (red[0] == 0u);
    int e = blockIdx.x * blockDim.x + t;
    if (e >= EE) return;
    if (is64) {
        g_src[e] = (int)raw[2 * e];
        g_dst[e] = (int)raw[2 * (EE + e)];
    } else {
        g_src[e] = (int)raw[e];
        g_dst[e] = (int)raw[EE + e];
    }
}

// inv_norm per node: 1 / max(||x_i||, 1e-12)
__global__ void k_norm(const float* __restrict__ x) {
    int i = blockIdx.x, t = threadIdx.x;  // 128 threads
    __shared__ float red[128];
    float4 v = ((const float4*)(x + i * DD))[t];
    float s = v.x * v.x + v.y * v.y + v.z * v.z + v.w * v.w;
    red[t] = s; __syncthreads();
    for (int d = 64; d > 0; d >>= 1) {
        if (t < d) red[t] += red[t + d];
        __syncthreads();
    }
    if (t == 0) g_inv[i] = 1.f / fmaxf(sqrtf(red[0]), 1e-12f);
}

// edge scatter: adjacency bitmask + degree counts
__global__ void k_edge() {
    int e = blockIdx.x * blockDim.x + threadIdx.x;
    if (e >= EE) return;
    int s = g_src[e], d = g_dst[e];
    atomicOr(&g_Abits[d * NWRD + (s >> 5)], 1u << (s & 31));
    atomicAdd(&g_deg_src[s], 1);
    atomicAdd(&g_deg_dst[d], 1);
}

// exclusive scan of 4096 ints -> off[0..4096]; block 0: src, block 1: dst
__global__ void k_scan2() {
    __shared__ int s[1024];
    const int* deg = (blockIdx.x == 0) ? g_deg_src : g_deg_dst;
    int* off = (blockIdx.x == 0) ? g_off_src : g_off_dst;
    int t = threadIdx.x;
    int v0 = deg[4 * t + 0], v1 = deg[4 * t + 1], v2 = deg[4 * t + 2], v3 = deg[4 * t + 3];
    int p1 = v0, p2 = v0 + v1, p3 = v0 + v1 + v2;
    int sum = p3 + v3;
    s[t] = sum; __syncthreads();
    for (int d = 1; d < 1024; d <<= 1) {
        int x = (t >= d) ? s[t - d] : 0;
        __syncthreads();
        s[t] += x;
        __syncthreads();
    }
    int base = s[t] - sum;  // exclusive
    off[4 * t + 0] = base;
    off[4 * t + 1] = base + p1;
    off[4 * t + 2] = base + p2;
    off[4 * t + 3] = base + p3;
    if (t == 1023) off[NN] = s[1023];
}

__global__ void k_fill() {
    int e = blockIdx.x * blockDim.x + threadIdx.x;
    if (e >= EE) return;
    int s = g_src[e];
    int p = atomicAdd(&g_cur_src[s], 1);
    g_csr_src[g_off_src[s] + p] = e;
    int d = g_dst[e];
    p = atomicAdd(&g_cur_dst[d], 1);
    g_csr_dst[g_off_dst[d] + p] = e;
}

// 2-hop boolean reachability rows: R_i = {i} | A_i | OR_{j in A_i} A_j
// also stores 1/|R_i| in g_cinv
__global__ void k_rbits() {
    int i = blockIdx.x, t = threadIdx.x;  // 128 threads
    __shared__ unsigned short list[4096];
    __shared__ int sc[128];
    unsigned w = g_Abits[i * NWRD + t];
    int pc = __popc(w);
    sc[t] = pc; __syncthreads();
    for (int d = 1; d < 128; d <<= 1) {
        int v = (t >= d) ? sc[t - d] : 0;
        __syncthreads();
        sc[t] += v;
        __syncthreads();
    }
    int total = sc[127];
    int o = sc[t] - pc;
    unsigned ww = w;
    while (ww) {
        int b = __ffs((int)ww) - 1;
        list[o++] = (unsigned short)(t * 32 + b);
        ww &= ww - 1;
    }
    __syncthreads();
    unsigned r = w;
    if (t == (i >> 5)) r |= 1u << (i & 31);
    for (int l = 0; l < total; l++) {
        int j = (int)list[l];
        r |= g_Abits[j * NWRD + t];
    }
    g_Rbits[i * NWRD + t] = r;
    __syncthreads();
    sc[t] = __popc(r);
    __syncthreads();
    for (int d = 64; d > 0; d >>= 1) {
        if (t < d) sc[t] += sc[t + d];
        __syncthreads();
    }
    if (t == 0) g_cinv[i] = 1.f / (float)sc[0];
}

// expand Rbits -> bf16 0/1 matrix (row per block, fully coalesced 32B stores)
__global__ void k_expandR() {
    int i = blockIdx.x;
    int t = threadIdx.x;  // 256: thread covers 16 consecutive bits (half a word)
    unsigned w = g_Rbits[i * NWRD + (t >> 1)];
    if (t & 1) w >>= 16;
    unsigned out[8];
#pragma unroll
    for (int b = 0; b < 8; b++) {
        unsigned p = 0;
        if ((w >> (2 * b)) & 1) p |= 0x3F80u;          // bf16 1.0 in low half
        if ((w >> (2 * b + 1)) & 1) p |= 0x3F800000u;  // bf16 1.0 in high half
        out[b] = p;
    }
    uint4* dst = (uint4*)(g_Rb16 + (size_t)i * NN + t * 16);
    dst[0] = make_uint4(out[0], out[1], out[2], out[3]);
    dst[1] = make_uint4(out[4], out[5], out[6], out[7]);
}

// x prep: transpose+split -> xt_hi/lo, and row-major split -> xh/xl (one read of x)
__global__ void k_xprep(const float* __restrict__ x) {
    __shared__ float tile[32][33];
    int bf = blockIdx.x * 32, bn = blockIdx.y * 32;
    int tx = threadIdx.x, ty = threadIdx.y;  // (32, 8)
    for (int r = ty; r < 32; r += 8) {
        float v = x[(size_t)(bn + r) * DD + bf + tx];
        tile[r][tx] = v;
        __nv_bfloat16 h = __float2bfloat16(v);
        g_xh[(size_t)(bn + r) * DD + bf + tx] = h;
        g_xl[(size_t)(bn + r) * DD + bf + tx] = __float2bfloat16(v - __bfloat162float(h));
    }
    __syncthreads();
    for (int r = ty; r < 32; r += 8) {
        float v = tile[tx][r];  // x[bn+tx][bf+r]
        __nv_bfloat16 h = __float2bfloat16(v);
        g_xt_hi[(size_t)(bf + r) * NN + bn + tx] = h;
        g_xt_lo[(size_t)(bf + r) * NN + bn + tx] = __float2bfloat16(v - __bfloat162float(h));
    }
}

// transpose+split weight W[K][N] -> Wt[N][K] bf16 hi/lo
__global__ void k_wt(const float* __restrict__ W, int K, int N,
                     __nv_bfloat16* __restrict__ oh, __nv_bfloat16* __restrict__ ol) {
    __shared__ float tile[32][33];
    int bk = blockIdx.x * 32, bn = blockIdx.y * 32;
    int tx = threadIdx.x, ty = threadIdx.y;  // (32, 8)
    for (int r = ty; r < 32; r += 8)
        tile[r][tx] = W[(size_t)(bk + r) * N + bn + tx];
    __syncthreads();
    for (int r = ty; r < 32; r += 8) {
        float v = tile[tx][r];  // W[bk+tx][bn+r]
        __nv_bfloat16 h = __float2bfloat16(v);
        ol[(size_t)(bn + r) * K + bk + tx] = __float2bfloat16(v - __bfloat162float(h));
        oh[(size_t)(bn + r) * K + bk + tx] = h;
    }
}

// batched version for the 4 encoder weights (all 512x512)
struct WPtrs { const float* W[4]; };
__global__ void k_wt4(WPtrs wp, __nv_bfloat16* __restrict__ oh, __nv_bfloat16* __restrict__ ol) {
    __shared__ float tile[32][33];
    int z = blockIdx.z;
    const float* W = wp.W[z];
    __nv_bfloat16* ohz = oh + (size_t)z * DD * HHH;
    __nv_bfloat16* olz = ol + (size_t)z * DD * HHH;
    int bk = blockIdx.x * 32, bn = blockIdx.y * 32;
    int tx = threadIdx.x, ty = threadIdx.y;
    for (int r = ty; r < 32; r += 8)
        tile[r][tx] = W[(size_t)(bk + r) * HHH + bn + tx];
    __syncthreads();
    for (int r = ty; r < 32; r += 8) {
        float v = tile[tx][r];
        __nv_bfloat16 h = __float2bfloat16(v);
        olz[(size_t)(bn + r) * DD + bk + tx] = __float2bfloat16(v - __bfloat162float(h));
        ohz[(size_t)(bn + r) * DD + bk + tx] = h;
    }
}

// ---------------- tensor-core GEMMs ----------------
#define MMA_BF16(c, a, b) asm volatile( \
    "mma.sync.aligned.m16n8k16.row.col.f32.bf16.bf16.f32 " \
    "{%0,%1,%2,%3}, {%4,%5,%6,%7}, {%8,%9}, {%0,%1,%2,%3};" \
    : "+f"(c[0]), "+f"(c[1]), "+f"(c[2]), "+f"(c[3]) \
    : "r"(a[0]), "r"(a[1]), "r"(a[2]), "r"(a[3]), "r"(b[0]), "r"(b[1]))

// ego = (R @ (x_hi + x_lo)) * cinv,  R bf16 exact 0/1. CTA 128x128, KT=32.
__global__ __launch_bounds__(256) void k_ego_mma(float* __restrict__ Cout) {
    extern __shared__ __nv_bfloat16 sm[];
    int tid = threadIdx.x;
    int lane = tid & 31, warp = tid >> 5;
    int wm = warp & 1, wn = warp >> 1;
    int br = blockIdx.x * 128, bc = blockIdx.y * 128;
    int g = lane >> 2, t4 = lane & 3;

    float acc[4][4][4];
#pragma unroll
    for (int mt = 0; mt < 4; mt++)
#pragma unroll
        for (int nt = 0; nt < 4; nt++)
#pragma unroll
            for (int q = 0; q < 4; q++) acc[mt][nt][q] = 0.f;

    auto copy_stage = [&](int s, int kb) {
        __nv_bfloat16* sb = sm + s * 3 * TSH;
#pragma unroll
        for (int c = 0; c < 2; c++) {
            int chunk = tid + c * 256;
            int row = chunk >> 2, seg = chunk & 3;
            int so = row * BSTRIDE + seg * 8;
            {
                unsigned da = (unsigned)__cvta_generic_to_shared(sb + so);
                const void* ga = g_Rb16 + (size_t)(br + row) * NN + kb + seg * 8;
                asm volatile("cp.async.ca.shared.global [%0], [%1], 16;" :: "r"(da), "l"(ga) : "memory");
            }
            {
                unsigned da = (unsigned)__cvta_generic_to_shared(sb + TSH + so);
                const void* ga = g_xt_hi + (size_t)(bc + row) * NN + kb + seg * 8;
                asm volatile("cp.async.ca.shared.global [%0], [%1], 16;" :: "r"(da), "l"(ga) : "memory");
            }
            {
                unsigned da = (unsigned)__cvta_generic_to_shared(sb + 2 * TSH + so);
                const void* ga = g_xt_lo + (size_t)(bc + row) * NN + kb + seg * 8;
                asm volatile("cp.async.ca.shared.global [%0], [%1], 16;" :: "r"(da), "l"(ga) : "memory");
            }
        }
        asm volatile("cp.async.commit_group;" ::: "memory");
    };

    const int KIT = NN / KT;
    copy_stage(0, 0);
    for (int kc = 0; kc < KIT; kc++) {
        if (kc + 1 < KIT) {
            copy_stage((kc + 1) & 1, (kc + 1) * KT);
            asm volatile("cp.async.wait_group 1;" ::: "memory");
        } else {
            asm volatile("cp.async.wait_group 0;" ::: "memory");
        }
        __syncthreads();
        const __nv_bfloat16* As = sm + (kc & 1) * 3 * TSH;
        const __nv_bfloat16* Bh = As + TSH;
        const __nv_bfloat16* Bl = Bh + TSH;
#pragma unroll
        for (int k0 = 0; k0 < KT; k0 += 16) {
            unsigned a[4][4], bh[4][2], bl[4][2];
#pragma unroll
            for (int mt = 0; mt < 4; mt++) {
                const __nv_bfloat16* p0 = As + (wm * 64 + mt * 16 + g) * BSTRIDE + k0 + 2 * t4;
                a[mt][0] = *(const unsigned*)p0;
                a[mt][1] = *(const unsigned*)(p0 + 8 * BSTRIDE);
                a[mt][2] = *(const unsigned*)(p0 + 8);
                a[mt][3] = *(const unsigned*)(p0 + 8 * BSTRIDE + 8);
            }
#pragma unroll
            for (int nt = 0; nt < 4; nt++) {
                const __nv_bfloat16* p0 = Bh + (wn * 32 + nt * 8 + g) * BSTRIDE + k0 + 2 * t4;
                bh[nt][0] = *(const unsigned*)p0;
                bh[nt][1] = *(const unsigned*)(p0 + 8);
                const __nv_bfloat16* p1 = Bl + (wn * 32 + nt * 8 + g) * BSTRIDE + k0 + 2 * t4;
                bl[nt][0] = *(const unsigned*)p1;
                bl[nt][1] = *(const unsigned*)(p1 + 8);
            }
#pragma unroll
            for (int mt = 0; mt < 4; mt++)
#pragma unroll
                for (int nt = 0; nt < 4; nt++) {
                    MMA_BF16(acc[mt][nt], a[mt], bh[nt]);
                    MMA_BF16(acc[mt][nt], a[mt], bl[nt]);
                }
        }
        __syncthreads();
    }

#pragma unroll
    for (int mt = 0; mt < 4; mt++) {
        int row0 = br + wm * 64 + mt * 16 + g;
        float i0 = g_cinv[row0];
        float i1 = g_cinv[row0 + 8];
#pragma unroll
        for (int nt = 0; nt < 4; nt++) {
            int col = bc + wn * 32 + nt * 8 + 2 * t4;
            float2 v0 = make_float2(acc[mt][nt][0] * i0, acc[mt][nt][1] * i0);
            float2 v1 = make_float2(acc[mt][nt][2] * i1, acc[mt][nt][3] * i1);
            *(float2*)&Cout[(size_t)row0 * DD + col] = v0;
            *(float2*)&Cout[(size_t)(row0 + 8) * DD + col] = v1;
        }
    }
}

// batched 4-way encoder GEMM: z selects feature. C = op(A_z @ B_z^T + s*bias_z),
// hi/lo 3-product split, output bf16 hi/lo into comb columns [z*HHH, z*HHH+HHH).
struct MmaB {
    const __nv_bfloat16 *Ah[4], *Al[4], *Bh[4], *Bl[4];
    const float* bias[4];
    const int* deg[4];
    int relu[4];
};
__global__ __launch_bounds__(256) void k_mma4(MmaB P,
    __nv_bfloat16* __restrict__ Ch, __nv_bfloat16* __restrict__ Cl) {
    extern __shared__ __nv_bfloat16 sm[];
    const int SSZ = 512 * BSTRIDE;
    int z = blockIdx.z;
    const __nv_bfloat16* Ah = P.Ah[z];
    const __nv_bfloat16* Al = P.Al[z];
    const __nv_bfloat16* Bh = P.Bh[z];
    const __nv_bfloat16* Bl = P.Bl[z];
    const float* bias = P.bias[z];
    const int* deg = P.deg[z];
    int relu = P.relu[z];
    int tid = threadIdx.x;
    int lane = tid & 31, warp = tid >> 5;
    int wm = warp & 1, wn = warp >> 1;
    int br = blockIdx.x * 128, bc = blockIdx.y * 128;
    int g = lane >> 2, t4 = lane & 3;

    float acc[4][4][4];
#pragma unroll
    for (int mt = 0; mt < 4; mt++)
#pragma unroll
        for (int nt = 0; nt < 4; nt++)
#pragma unroll
            for (int q = 0; q < 4; q++) acc[mt][nt][q] = 0.f;

    auto copy_stage = [&](int s, int kb) {
        __nv_bfloat16* sb = sm + s * SSZ;
#pragma unroll
        for (int c = 0; c < 8; c++) {
            int chunk = tid + c * 256;
            int row = chunk >> 2, seg = chunk & 3;
            const __nv_bfloat16* gp;
            if (row < 128)      gp = Ah + (size_t)(br + row) * DD;
            else if (row < 256) gp = Al + (size_t)(br + row - 128) * DD;
            else if (row < 384) gp = Bh + (size_t)(bc + row - 256) * DD;
            else                gp = Bl + (size_t)(bc + row - 384) * DD;
            unsigned da = (unsigned)__cvta_generic_to_shared(sb + row * BSTRIDE + seg * 8);
            asm volatile("cp.async.ca.shared.global [%0], [%1], 16;"
                         :: "r"(da), "l"(gp + kb + seg * 8) : "memory");
        }
        asm volatile("cp.async.commit_group;" ::: "memory");
    };

    const int KIT = DD / KT;
    copy_stage(0, 0);
    for (int kc = 0; kc < KIT; kc++) {
        if (kc + 1 < KIT) {
            copy_stage((kc + 1) & 1, (kc + 1) * KT);
            asm volatile("cp.async.wait_group 1;" ::: "memory");
        } else {
            asm volatile("cp.async.wait_group 0;" ::: "memory");
        }
        __syncthreads();
        const __nv_bfloat16* sAh = sm + (kc & 1) * SSZ;
        const __nv_bfloat16* sAl = sAh + 128 * BSTRIDE;
        const __nv_bfloat16* sBh = sAl + 128 * BSTRIDE;
        const __nv_bfloat16* sBl = sBh + 128 * BSTRIDE;
#pragma unroll
        for (int k0 = 0; k0 < KT; k0 += 16) {
            unsigned ah[4][4], al[4][4], bh[4][2], bl[4][2];
#pragma unroll
            for (int mt = 0; mt < 4; mt++) {
                int ro = (wm * 64 + mt * 16 + g) * BSTRIDE + k0 + 2 * t4;
                ah[mt][0] = *(const unsigned*)(sAh + ro);
                ah[mt][1] = *(const unsigned*)(sAh + ro + 8 * BSTRIDE);
                ah[mt][2] = *(const unsigned*)(sAh + ro + 8);
                ah[mt][3] = *(const unsigned*)(sAh + ro + 8 * BSTRIDE + 8);
                al[mt][0] = *(const unsigned*)(sAl + ro);
                al[mt][1] = *(const unsigned*)(sAl + ro + 8 * BSTRIDE);
                al[mt][2] = *(const unsigned*)(sAl + ro + 8);
                al[mt][3] = *(const unsigned*)(sAl + ro + 8 * BSTRIDE + 8);
            }
#pragma unroll
            for (int nt = 0; nt < 4; nt++) {
                int ro = (wn * 32 + nt * 8 + g) * BSTRIDE + k0 + 2 * t4;
                bh[nt][0] = *(const unsigned*)(sBh + ro);
                bh[nt][1] = *(const unsigned*)(sBh + ro + 8);
                bl[nt][0] = *(const unsigned*)(sBl + ro);
                bl[nt][1] = *(const unsigned*)(sBl + ro + 8);
            }
#pragma unroll
            for (int mt = 0; mt < 4; mt++)
#pragma unroll
                for (int nt = 0; nt < 4; nt++) {
                    MMA_BF16(acc[mt][nt], ah[mt], bh[nt]);
                    MMA_BF16(acc[mt][nt], ah[mt], bl[nt]);
                    MMA_BF16(acc[mt][nt], al[mt], bh[nt]);
                }
        }
        __syncthreads();
    }

#pragma unroll
    for (int mt = 0; mt < 4; mt++) {
        int row0 = br + wm * 64 + mt * 16 + g;
        float s0 = deg ? (float)deg[row0] : 1.f;
        float s1 = deg ? (float)deg[row0 + 8] : 1.f;
#pragma unroll
        for (int nt = 0; nt < 4; nt++) {
            int col = bc + wn * 32 + nt * 8 + 2 * t4;
            float b0 = bias[col], b1 = bias[col + 1];
            float v00 = acc[mt][nt][0] + s0 * b0, v01 = acc[mt][nt][1] + s0 * b1;
            float v10 = acc[mt][nt][2] + s1 * b0, v11 = acc[mt][nt][3] + s1 * b1;
            if (relu) {
                v00 = fmaxf(v00, 0.f); v01 = fmaxf(v01, 0.f);
                v10 = fmaxf(v10, 0.f); v11 = fmaxf(v11, 0.f);
            }
            size_t o0 = (size_t)row0 * (4 * HHH) + z * HHH + col;
            size_t o1 = (size_t)(row0 + 8) * (4 * HHH) + z * HHH + col;
            __nv_bfloat162 h0, l0, h1, l1;
            h0.x = __float2bfloat16(v00); h0.y = __float2bfloat16(v01);
            l0.x = __float2bfloat16(v00 - __bfloat162float(h0.x));
            l0.y = __float2bfloat16(v01 - __bfloat162float(h0.y));
            h1.x = __float2bfloat16(v10); h1.y = __float2bfloat16(v11);
            l1.x = __float2bfloat16(v10 - __bfloat162float(h1.x));
            l1.y = __float2bfloat16(v11 - __bfloat162float(h1.y));
            *(__nv_bfloat162*)&Ch[o0] = h0;
            *(__nv_bfloat162*)&Cl[o0] = l0;
            *(__nv_bfloat162*)&Ch[o1] = h1;
            *(__nv_bfloat162*)&Cl[o1] = l1;
        }
    }
}

// fc GEMM (BN=64, fp32 out): logits = comb @ Wfc^T + b
__global__ __launch_bounds__(256) void k_mma_fc(
    const __nv_bfloat16* __restrict__ Ah, const __nv_bfloat16* __restrict__ Al,
    const __nv_bfloat16* __restrict__ Bh, const __nv_bfloat16* __restrict__ Bl,
    const float* __restrict__ bias, float* __restrict__ Cf) {
    extern __shared__ __nv_bfloat16 sm[];
    const int K = 4 * HHH;
    const int SSZ = 384 * BSTRIDE;
    int tid = threadIdx.x;
    int lane = tid & 31, warp = tid >> 5;
    int wm = warp & 1, wn = warp >> 1;
    int br = blockIdx.x * 128, bc = 0;
    int g = lane >> 2, t4 = lane & 3;

    float acc[4][2][4];
#pragma unroll
    for (int mt = 0; mt < 4; mt++)
#pragma unroll
        for (int nt = 0; nt < 2; nt++)
#pragma unroll
            for (int q = 0; q < 4; q++) acc[mt][nt][q] = 0.f;

    auto copy_stage = [&](int s, int kb) {
        __nv_bfloat16* sb = sm + s * SSZ;
#pragma unroll
        for (int c = 0; c < 6; c++) {
            int chunk = tid + c * 256;
            int row = chunk >> 2, seg = chunk & 3;
            const __nv_bfloat16* gp;
            if (row < 128)      gp = Ah + (size_t)(br + row) * K;
            else if (row < 256) gp = Al + (size_t)(br + row - 128) * K;
            else if (row < 320) gp = Bh + (size_t)(bc + row - 256) * K;
            else                gp = Bl + (size_t)(bc + row - 320) * K;
            unsigned da = (unsigned)__cvta_generic_to_shared(sb + row * BSTRIDE + seg * 8);
            asm volatile("cp.async.ca.shared.global [%0], [%1], 16;"
                         :: "r"(da), "l"(gp + kb + seg * 8) : "memory");
        }
        asm volatile("cp.async.commit_group;" ::: "memory");
    };

    const int KIT = K / KT;
    copy_stage(0, 0);
    for (int kc = 0; kc < KIT; kc++) {
        if (kc + 1 < KIT) {
            copy_stage((kc + 1) & 1, (kc + 1) * KT);
            asm volatile("cp.async.wait_group 1;" ::: "memory");
        } else {
            asm volatile("cp.async.wait_group 0;" ::: "memory");
        }
        __syncthreads();
        const __nv_bfloat16* sAh = sm + (kc & 1) * SSZ;
        const __nv_bfloat16* sAl = sAh + 128 * BSTRIDE;
        const __nv_bfloat16* sBh = sAl + 128 * BSTRIDE;
        const __nv_bfloat16* sBl = sBh + 64 * BSTRIDE;
#pragma unroll
        for (int k0 = 0; k0 < KT; k0 += 16) {
            unsigned ah[4][4], al[4][4], bh[2][2], bl[2][2];
#pragma unroll
            for (int mt = 0; mt < 4; mt++) {
                int ro = (wm * 64 + mt * 16 + g) * BSTRIDE + k0 + 2 * t4;
                ah[mt][0] = *(const unsigned*)(sAh + ro);
                ah[mt][1] = *(const unsigned*)(sAh + ro + 8 * BSTRIDE);
                ah[mt][2] = *(const unsigned*)(sAh + ro + 8);
                ah[mt][3] = *(const unsigned*)(sAh + ro + 8 * BSTRIDE + 8);
                al[mt][0] = *(const unsigned*)(sAl + ro);
                al[mt][1] = *(const unsigned*)(sAl + ro + 8 * BSTRIDE);
                al[mt][2] = *(const unsigned*)(sAl + ro + 8);
                al[mt][3] = *(const unsigned*)(sAl + ro + 8 * BSTRIDE + 8);
            }
#pragma unroll
            for (int nt = 0; nt < 2; nt++) {
                int ro = (wn * 16 + nt * 8 + g) * BSTRIDE + k0 + 2 * t4;
                bh[nt][0] = *(const unsigned*)(sBh + ro);
                bh[nt][1] = *(const unsigned*)(sBh + ro + 8);
                bl[nt][0] = *(const unsigned*)(sBl + ro);
                bl[nt][1] = *(const unsigned*)(sBl + ro + 8);
            }
#pragma unroll
            for (int mt = 0; mt < 4; mt++)
#pragma unroll
                for (int nt = 0; nt < 2; nt++) {
                    MMA_BF16(acc[mt][nt], ah[mt], bh[nt]);
                    MMA_BF16(acc[mt][nt], ah[mt], bl[nt]);
                    MMA_BF16(acc[mt][nt], al[mt], bh[nt]);
                }
        }
        __syncthreads();
    }

#pragma unroll
    for (int mt = 0; mt < 4; mt++) {
        int row0 = br + wm * 64 + mt * 16 + g;
#pragma unroll
        for (int nt = 0; nt < 2; nt++) {
            int col = wn * 16 + nt * 8 + 2 * t4;
            float b0 = bias[col], b1 = bias[col + 1];
            *(float2*)&Cf[(size_t)row0 * OUTC + col] =
                make_float2(acc[mt][nt][0] + b0, acc[mt][nt][1] + b1);
            *(float2*)&Cf[(size_t)(row0 + 8) * OUTC + col] =
                make_float2(acc[mt][nt][2] + b0, acc[mt][nt][3] + b1);
        }
    }
}

// per-edge cosine similarity (float4 loads)
__global__ void k_cos_edge(const float* __restrict__ x) {
    int e = blockIdx.x * 8 + (threadIdx.x >> 5);
    int lane = threadIdx.x & 31;
    int s = g_src[e], d = g_dst[e];
    const float4* xs = (const float4*)(x + s * DD);
    const float4* xd = (const float4*)(x + d * DD);
    float acc = 0.f;
#pragma unroll
    for (int u = 0; u < 4; u++) {
        float4 a = xs[lane + 32 * u];
        float4 b = xd[lane + 32 * u];
        acc += a.x * b.x + a.y * b.y + a.z * b.z + a.w * b.w;
    }
    for (int o = 16; o > 0; o >>= 1) acc += __shfl_xor_sync(0xffffffffu, acc, o);
    if (lane == 0) g_cose[e] = acc * g_inv[s] * g_inv[d];
}

// fused: per-node softmax stats + cut & cosine feature accumulation (float4)
__global__ void k_cutcos(const float* __restrict__ x, const float* __restrict__ wgt) {
    int i = blockIdx.x, t = threadIdx.x;  // 128
    int beg = g_off_src[i];
    int deg = g_off_src[i + 1] - beg;
    __shared__ float red[128];
    float mx = -1e30f;
    for (int l = t; l < deg; l += 128) mx = fmaxf(mx, g_cose[g_csr_src[beg + l]]);
    red[t] = mx; __syncthreads();
    for (int d = 64; d > 0; d >>= 1) {
        if (t < d) red[t] = fmaxf(red[t], red[t + d]);
        __syncthreads();
    }
    float m = (deg > 0) ? red[0] : 0.f;
    __syncthreads();
    float sp = 0.f;
    for (int l = t; l < deg; l += 128) sp += expf(g_cose[g_csr_src[beg + l]] - m);
    red[t] = sp; __syncthreads();
    for (int d = 64; d > 0; d >>= 1) {
        if (t < d) red[t] += red[t + d];
        __syncthreads();
    }
    float den = red[0];
    float dsafe = (deg > 0 && den > 0.f) ? den : 1.f;
    __syncthreads();
    float wp = 0.f;
    for (int l = t; l < deg; l += 128) wp += wgt[g_csr_src[beg + l]];
    red[t] = wp; __syncthreads();
    for (int d = 64; d > 0; d >>= 1) {
        if (t < d) red[t] += red[t + d];
        __syncthreads();
    }
    float wsum = red[0];
    __syncthreads();
    __shared__ int sd[128];
    __shared__ float sw[128];
    __shared__ float sa[128];
    float4 ac = make_float4(0.f, 0.f, 0.f, 0.f);
    float4 as = make_float4(0.f, 0.f, 0.f, 0.f);
    float tot = 0.f;
    for (int base = 0; base < deg; base += 128) {
        int l = base + t;
        if (l < deg) {
            int e = g_csr_src[beg + l];
            sd[t] = g_dst[e];
            sw[t] = wgt[e];
            sa[t] = expf(g_cose[e] - m) / dsafe;
        }
        __syncthreads();
        int lim = min(128, deg - base);
        for (int u = 0; u < lim; u++) {
            float4 v = ((const float4*)(x + sd[u] * DD))[t];
            float w1 = sw[u], w2 = sa[u];
            tot += w2;
            ac.x += w1 * v.x; ac.y += w1 * v.y; ac.z += w1 * v.z; ac.w += w1 * v.w;
            as.x += w2 * v.x; as.y += w2 * v.y; as.z += w2 * v.z; as.w += w2 * v.w;
        }
        __syncthreads();
    }
    bool use = (deg > 0) && (wsum > 0.f);
    float invc = use ? 1.f / wsum : 0.f;
    float tsafe = (tot > 0.f) ? tot : 1.f;
    float4 xv = ((const float4*)(x + i * DD))[t];
    float4 oc, os;
    oc.x = use ? ac.x * invc : xv.x;  oc.y = use ? ac.y * invc : xv.y;
    oc.z = use ? ac.z * invc : xv.z;  oc.w = use ? ac.w * invc : xv.w;
    float it = 1.f / tsafe;
    os.x = (deg > 0) ? as.x * it : xv.x;  os.y = (deg > 0) ? as.y * it : xv.y;
    os.z = (deg > 0) ? as.z * it : xv.z;  os.w = (deg > 0) ? as.w * it : xv.w;
    ((float4*)(g_cut + i * DD))[t] = oc;
    ((float4*)(g_cosf + i * DD))[t] = os;
}

// in-edge aggregation of cut + cosf (runs on s2, overlaps ego_mma)
__global__ void k_aggCS() {
    int i = blockIdx.x, t = threadIdx.x;  // 128, thread covers cols 4t..4t+3
    int beg = g_off_dst[i];
    int deg = g_off_dst[i + 1] - beg;
    __shared__ int ss[128];
    float4 aC = make_float4(0.f, 0.f, 0.f, 0.f);
    float4 aS = make_float4(0.f, 0.f, 0.f, 0.f);
    for (int base = 0; base < deg; base += 128) {
        int l = base + t;
        if (l < deg) ss[t] = g_src[g_csr_dst[beg + l]];
        __syncthreads();
        int lim = min(128, deg - base);
        for (int u = 0; u < lim; u++) {
            int b = ss[u] * DD;
            float4 vC = ((const float4*)(g_cut + b))[t];
            float4 vS = ((const float4*)(g_cosf + b))[t];
            aC.x += vC.x; aC.y += vC.y; aC.z += vC.z; aC.w += vC.w;
            aS.x += vS.x; aS.y += vS.y; aS.z += vS.z; aS.w += vS.w;
        }
        __syncthreads();
    }
    int col = i * DD + 4 * t;
    float vC[4] = {aC.x, aC.y, aC.z, aC.w};
    float vS[4] = {aS.x, aS.y, aS.z, aS.w};
#pragma unroll
    for (int c = 0; c < 4; c++) {
        __nv_bfloat16 h;
        h = __float2bfloat16(vC[c]);
        g_aggCh[col + c] = h; g_aggCl[col + c] = __float2bfloat16(vC[c] - __bfloat162float(h));
        h = __float2bfloat16(vS[c]);
        g_aggSh[col + c] = h; g_aggSl[col + c] = __float2bfloat16(vS[c] - __bfloat162float(h));
    }
}

// in-edge aggregation of ego (critical path, after ego_mma)
__global__ void k_aggE() {
    int i = blockIdx.x, t = threadIdx.x;
    int beg = g_off_dst[i];
    int deg = g_off_dst[i + 1] - beg;
    __shared__ int ss[128];
    float4 aE = make_float4(0.f, 0.f, 0.f, 0.f);
    for (int base = 0; base < deg; base += 128) {
        int l = base + t;
        if (l < deg) ss[t] = g_src[g_csr_dst[beg + l]];
        __syncthreads();
        int lim = min(128, deg - base);
        for (int u = 0; u < lim; u++) {
            float4 vE = ((const float4*)(g_ego + ss[u] * DD))[t];
            aE.x += vE.x; aE.y += vE.y; aE.z += vE.z; aE.w += vE.w;
        }
        __syncthreads();
    }
    int col = i * DD + 4 * t;
    float vE[4] = {aE.x, aE.y, aE.z, aE.w};
#pragma unroll
    for (int c = 0; c < 4; c++) {
        __nv_bfloat16 h = __float2bfloat16(vE[c]);
        g_aggEh[col + c] = h;
        g_aggEl[col + c] = __float2bfloat16(vE[c] - __bfloat162float(h));
    }
}

// row-wise log_softmax over 64 logits; warp per row
__global__ void k_lsm(float* __restrict__ out) {
    int row = blockIdx.x * 4 + (threadIdx.x >> 5);
    int lane = threadIdx.x & 31;
    float v0 = g_logits[row * OUTC + lane];
    float v1 = g_logits[row * OUTC + 32 + lane];
    float m = fmaxf(v0, v1);
    for (int o = 16; o > 0; o >>= 1) m = fmaxf(m, __shfl_xor_sync(0xffffffffu, m, o));
    float s = expf(v0 - m) + expf(v1 - m);
    for (int o = 16; o > 0; o >>= 1) s += __shfl_xor_sync(0xffffffffu, s, o);
    float l = m + logf(s);
    out[row * OUTC + lane] = v0 - l;
    out[row * OUTC + 32 + lane] = v1 - l;
}

// ---------------- launcher ----------------
extern "C" void kernel_launch(void* const* d_in, const int* in_sizes, int n_in,
                              void* d_out, int out_size) {
    const float* x      = (const float*)d_in[0];
    const unsigned* raw = (const unsigned*)d_in[1];
    const float* ew     = (const float*)d_in[2];
    const float* W_ego  = (const float*)d_in[3];
    const float* b_ego  = (const float*)d_in[4];
    const float* W_cut  = (const float*)d_in[5];
    const float* b_cut  = (const float*)d_in[6];
    const float* W_cos  = (const float*)d_in[7];
    const float* b_cos  = (const float*)d_in[8];
    const float* W_glob = (const float*)d_in[9];
    const float* b_glob = (const float*)d_in[10];
    const float* W_fc   = (const float*)d_in[11];
    const float* b_fc   = (const float*)d_in[12];
    float* out = (float*)d_out;

    float *p_logits, *p_ego;
    int *p_degdst;
    cudaGetSymbolAddress((void**)&p_logits, g_logits);
    cudaGetSymbolAddress((void**)&p_ego, g_ego);
    cudaGetSymbolAddress((void**)&p_degdst, g_deg_dst);
    __nv_bfloat16 *p_aEh, *p_aEl, *p_aCh, *p_aCl, *p_aSh, *p_aSl;
    __nv_bfloat16 *p_xh, *p_xl, *p_ch, *p_cl, *p_Wth, *p_Wtl;
    cudaGetSymbolAddress((void**)&p_aEh, g_aggEh);
    cudaGetSymbolAddress((void**)&p_aEl, g_aggEl);
    cudaGetSymbolAddress((void**)&p_aCh, g_aggCh);
    cudaGetSymbolAddress((void**)&p_aCl, g_aggCl);
    cudaGetSymbolAddress((void**)&p_aSh, g_aggSh);
    cudaGetSymbolAddress((void**)&p_aSl, g_aggSl);
    cudaGetSymbolAddress((void**)&p_xh, g_xh);
    cudaGetSymbolAddress((void**)&p_xl, g_xl);
    cudaGetSymbolAddress((void**)&p_ch, g_combh);
    cudaGetSymbolAddress((void**)&p_cl, g_combl);
    cudaGetSymbolAddress((void**)&p_Wth, g_Wth);
    cudaGetSymbolAddress((void**)&p_Wtl, g_Wtl);

    static const size_t EGO_SMEM = 2 * 3 * TSH * sizeof(__nv_bfloat16);            // 61440
    static const size_t MMA4_SMEM = 2 * 512 * BSTRIDE * sizeof(__nv_bfloat16);     // 81920
    static const size_t FC_SMEM  = 2 * 384 * BSTRIDE * sizeof(__nv_bfloat16);      // 61440
    cudaFuncSetAttribute(k_ego_mma, cudaFuncAttributeMaxDynamicSharedMemorySize, (int)EGO_SMEM);
    cudaFuncSetAttribute(k_mma4, cudaFuncAttributeMaxDynamicSharedMemorySize, (int)MMA4_SMEM);
    cudaFuncSetAttribute(k_mma_fc, cudaFuncAttributeMaxDynamicSharedMemorySize, (int)FC_SMEM);

    // worker streams + fork/join events, created once (outside graph capture)
    static cudaStream_t s1 = 0, s2 = 0;
    static cudaEvent_t evRoot = 0, evConv = 0, evEdge = 0, evXprep = 0, evWt = 0;
    static cudaEvent_t evFill = 0, evCS = 0;
    if (!s1) {
        cudaStreamCreateWithFlags(&s1, cudaStreamNonBlocking);
        cudaStreamCreateWithFlags(&s2, cudaStreamNonBlocking);
        cudaEventCreateWithFlags(&evRoot, cudaEventDisableTiming);
        cudaEventCreateWithFlags(&evConv, cudaEventDisableTiming);
        cudaEventCreateWithFlags(&evEdge, cudaEventDisableTiming);
        cudaEventCreateWithFlags(&evXprep, cudaEventDisableTiming);
        cudaEventCreateWithFlags(&evWt, cudaEventDisableTiming);
        cudaEventCreateWithFlags(&evFill, cudaEventDisableTiming);
        cudaEventCreateWithFlags(&evCS, cudaEventDisableTiming);
    }

    // fork
    cudaEventRecord(evRoot, 0);
    cudaStreamWaitEvent(s1, evRoot, 0);
    cudaStreamWaitEvent(s2, evRoot, 0);

    // --- s1: input-only prep (x splits + weight transposes) ---
    k_xprep<<<dim3(DD / 32, NN / 32), dim3(32, 8), 0, s1>>>(x);
    cudaEventRecord(evXprep, s1);
    {
        WPtrs wp; wp.W[0] = W_ego; wp.W[1] = W_cut; wp.W[2] = W_cos; wp.W[3] = W_glob;
        k_wt4<<<dim3(DD / 32, HHH / 32, 4), dim3(32, 8), 0, s1>>>(wp, p_Wth, p_Wtl);
    }
    k_wt<<<dim3(4 * HHH / 32, OUTC / 32), dim3(32, 8), 0, s1>>>(
        W_fc, 4 * HHH, OUTC, p_Wth + WT_FC_OFF, p_Wtl + WT_FC_OFF);
    cudaEventRecord(evWt, s1);

    // --- s0: graph build ---
    k_norm<<<NN, 128, 0, s2>>>(x);
    k_zero<<<512, 1024>>>();
    k_convert<<<EE / 256, 256>>>(raw);
    cudaEventRecord(evConv, 0);
    k_edge<<<EE / 256, 256>>>();
    cudaEventRecord(evEdge, 0);

    // --- s2: cosine/CSR path (cos_edge needs only convert + norm) ---
    cudaStreamWaitEvent(s2, evConv, 0);
    k_cos_edge<<<EE / 8, 256, 0, s2>>>(x);
    cudaStreamWaitEvent(s2, evEdge, 0);
    k_scan2<<<2, 1024, 0, s2>>>();
    k_fill<<<EE / 256, 256, 0, s2>>>();
    cudaEventRecord(evFill, s2);
    k_cutcos<<<NN, 128, 0, s2>>>(x, ew);
    k_aggCS<<<NN, 128, 0, s2>>>();
    cudaEventRecord(evCS, s2);

    // --- s0: ego path ---
    k_rbits<<<NN, 128>>>();
    k_expandR<<<NN, 256>>>();
    cudaStreamWaitEvent(0, evXprep, 0);
    k_ego_mma<<<dim3(NN / 128, DD / 128), 256, EGO_SMEM>>>(p_ego);

    // join: ego aggregation + encoder GEMMs + epilogue
    cudaStreamWaitEvent(0, evFill, 0);
    k_aggE<<<NN, 128>>>();
    cudaStreamWaitEvent(0, evCS, 0);
    cudaStreamWaitEvent(0, evWt, 0);
    {
        MmaB P;
        P.Ah[0] = p_aEh; P.Al[0] = p_aEl;
        P.Ah[1] = p_aCh; P.Al[1] = p_aCl;
        P.Ah[2] = p_aSh; P.Al[2] = p_aSl;
        P.Ah[3] = p_xh;  P.Al[3] = p_xl;
        for (int z = 0; z < 4; z++) {
            P.Bh[z] = p_Wth + (size_t)z * DD * HHH;
            P.Bl[z] = p_Wtl + (size_t)z * DD * HHH;
        }
        P.bias[0] = b_ego; P.bias[1] = b_cut; P.bias[2] = b_cos; P.bias[3] = b_glob;
        P.deg[0] = p_degdst; P.deg[1] = p_degdst; P.deg[2] = p_degdst; P.deg[3] = (const int*)0;
        P.relu[0] = 1; P.relu[1] = 1; P.relu[2] = 1; P.relu[3] = 0;
        k_mma4<<<dim3(NN / 128, HHH / 128, 4), 256, MMA4_SMEM>>>(P, p_ch, p_cl);
    }
    k_mma_fc<<<NN / 128, 256, FC_SMEM>>>(p_ch, p_cl, p_Wth + WT_FC_OFF, p_Wtl + WT_FC_OFF,
                                         b_fc, p_logits);
    k_lsm<<<NN / 4, 128>>>(out);

    (void)in_sizes; (void)n_in; (void)out_size;
}

// round 13
// speedup vs baseline: 1.2313x; 1.2313x over previous
#include <cuda_runtime.h>
#include <cuda_bf16.h>
#include <math.h>

#define NN 4096
#define EE 131072
#define DD 512
#define HHH 512
#define OUTC 64
#define NWRD 128   // 4096 bits / 32
#define KT 32
#define BSTRIDE 40        // smem row stride in halves (80B = 16B-aligned rows)
#define TSH (128 * BSTRIDE)

// ---------------- scratch (device globals; no allocations) ----------------
__device__ unsigned g_Abits[NN * NWRD];
__device__ unsigned g_Rbits[NN * NWRD];
__device__ float g_cinv[NN];
__device__ int g_src[EE], g_dst[EE];
__device__ int g_deg_src[NN], g_deg_dst[NN];
__device__ int g_off_src[NN + 1], g_off_dst[NN + 1];
__device__ int g_cur_src[NN], g_cur_dst[NN];
__device__ int g_csr_src[EE], g_csr_dst[EE];
__device__ float g_inv[NN];
__device__ float g_cose[EE];
__device__ float g_ego[NN * DD], g_cut[NN * DD], g_cosf[NN * DD];
__device__ float g_logits[NN * OUTC];
// tensor-core buffers (bf16 hi/lo splits)
__device__ __nv_bfloat16 g_Rb16[(size_t)NN * NN];   // 32 MB, R as exact 0/1 bf16
__device__ __nv_bfloat16 g_xt_hi[(size_t)DD * NN];  // x^T hi split [feature][node]
__device__ __nv_bfloat16 g_xt_lo[(size_t)DD * NN];
__device__ __nv_bfloat16 g_xh[NN * DD], g_xl[NN * DD];          // x row-major split
__device__ __nv_bfloat16 g_aggEh[NN * DD], g_aggEl[NN * DD];
__device__ __nv_bfloat16 g_aggCh[NN * DD], g_aggCl[NN * DD];
__device__ __nv_bfloat16 g_aggSh[NN * DD], g_aggSl[NN * DD];
__device__ __nv_bfloat16 g_combh[(size_t)NN * 4 * HHH], g_combl[(size_t)NN * 4 * HHH];
// transposed+split weights: 4 encoder weights [HHH][DD] then fc [OUTC][4*HHH]
#define WT_FC_OFF (4 * DD * HHH)
__device__ __nv_bfloat16 g_Wth[4 * DD * HHH + OUTC * 4 * HHH];
__device__ __nv_bfloat16 g_Wtl[4 * DD * HHH + OUTC * 4 * HHH];

// ---------------- setup kernels ----------------

__global__ void k_zero() {
    int idx = blockIdx.x * blockDim.x + threadIdx.x;
    for (int i = idx; i < NN * NWRD; i += gridDim.x * blockDim.x) g_Abits[i] = 0u;
    if (idx < NN) {
        g_deg_src[idx] = 0; g_deg_dst[idx] = 0;
        g_cur_src[idx] = 0; g_cur_dst[idx] = 0;
    }
}

// convert edge_index, with per-block int64/int32 detection (odd words of the
// first 256 entries all zero => int64)
__global__ void k_convert(const unsigned* __restrict__ raw) {
    __shared__ unsigned red[256];
    int t = threadIdx.x;
    red[t] = raw[2 * t + 1];
    __syncthreads();
    for (int d = 128; d > 0; d >>= 1) {
        if (t < d) red[t] |= red[t + d];
        __syncthreads();
    }
    int is64 = (red[0] == 0u);
    int e = blockIdx.x * blockDim.x + t;
    if (e >= EE) return;
    if (is64) {
        g_src[e] = (int)raw[2 * e];
        g_dst[e] = (int)raw[2 * (EE + e)];
    } else {
        g_src[e] = (int)raw[e];
        g_dst[e] = (int)raw[EE + e];
    }
}

// inv_norm per node: 1 / max(||x_i||, 1e-12)
__global__ void k_norm(const float* __restrict__ x) {
    int i = blockIdx.x, t = threadIdx.x;  // 128 threads
    __shared__ float red[128];
    float4 v = ((const float4*)(x + i * DD))[t];
    float s = v.x * v.x + v.y * v.y + v.z * v.z + v.w * v.w;
    red[t] = s; __syncthreads();
    for (int d = 64; d > 0; d >>= 1) {
        if (t < d) red[t] += red[t + d];
        __syncthreads();
    }
    if (t == 0) g_inv[i] = 1.f / fmaxf(sqrtf(red[0]), 1e-12f);
}

// edge scatter: adjacency bitmask + degree counts
__global__ void k_edge() {
    int e = blockIdx.x * blockDim.x + threadIdx.x;
    if (e >= EE) return;
    int s = g_src[e], d = g_dst[e];
    atomicOr(&g_Abits[d * NWRD + (s >> 5)], 1u << (s & 31));
    atomicAdd(&g_deg_src[s], 1);
    atomicAdd(&g_deg_dst[d], 1);
}

// exclusive scan of 4096 ints -> off[0..4096]; block 0: src, block 1: dst
__global__ void k_scan2() {
    __shared__ int s[1024];
    const int* deg = (blockIdx.x == 0) ? g_deg_src : g_deg_dst;
    int* off = (blockIdx.x == 0) ? g_off_src : g_off_dst;
    int t = threadIdx.x;
    int v0 = deg[4 * t + 0], v1 = deg[4 * t + 1], v2 = deg[4 * t + 2], v3 = deg[4 * t + 3];
    int p1 = v0, p2 = v0 + v1, p3 = v0 + v1 + v2;
    int sum = p3 + v3;
    s[t] = sum; __syncthreads();
    for (int d = 1; d < 1024; d <<= 1) {
        int x = (t >= d) ? s[t - d] : 0;
        __syncthreads();
        s[t] += x;
        __syncthreads();
    }
    int base = s[t] - sum;  // exclusive
    off[4 * t + 0] = base;
    off[4 * t + 1] = base + p1;
    off[4 * t + 2] = base + p2;
    off[4 * t + 3] = base + p3;
    if (t == 1023) off[NN] = s[1023];
}

__global__ void k_fill() {
    int e = blockIdx.x * blockDim.x + threadIdx.x;
    if (e >= EE) return;
    int s = g_src[e];
    int p = atomicAdd(&g_cur_src[s], 1);
    g_csr_src[g_off_src[s] + p] = e;
    int d = g_dst[e];
    p = atomicAdd(&g_cur_dst[d], 1);
    g_csr_dst[g_off_dst[d] + p] = e;
}

// 2-hop boolean reachability rows: R_i = {i} | A_i | OR_{j in A_i} A_j
// also stores 1/|R_i| in g_cinv
__global__ void k_rbits() {
    int i = blockIdx.x, t = threadIdx.x;  // 128 threads
    __shared__ unsigned short list[4096];
    __shared__ int sc[128];
    unsigned w = g_Abits[i * NWRD + t];
    int pc = __popc(w);
    sc[t] = pc; __syncthreads();
    for (int d = 1; d < 128; d <<= 1) {
        int v = (t >= d) ? sc[t - d] : 0;
        __syncthreads();
        sc[t] += v;
        __syncthreads();
    }
    int total = sc[127];
    int o = sc[t] - pc;
    unsigned ww = w;
    while (ww) {
        int b = __ffs((int)ww) - 1;
        list[o++] = (unsigned short)(t * 32 + b);
        ww &= ww - 1;
    }
    __syncthreads();
    unsigned r = w;
    if (t == (i >> 5)) r |= 1u << (i & 31);
    for (int l = 0; l < total; l++) {
        int j = (int)list[l];
        r |= g_Abits[j * NWRD + t];
    }
    g_Rbits[i * NWRD + t] = r;
    __syncthreads();
    sc[t] = __popc(r);
    __syncthreads();
    for (int d = 64; d > 0; d >>= 1) {
        if (t < d) sc[t] += sc[t + d];
        __syncthreads();
    }
    if (t == 0) g_cinv[i] = 1.f / (float)sc[0];
}

// expand Rbits -> bf16 0/1 matrix (row per block, fully coalesced 32B stores)
__global__ void k_expandR() {
    int i = blockIdx.x;
    int t = threadIdx.x;  // 256: thread covers 16 consecutive bits (half a word)
    unsigned w = g_Rbits[i * NWRD + (t >> 1)];
    if (t & 1) w >>= 16;
    unsigned out[8];
#pragma unroll
    for (int b = 0; b < 8; b++) {
        unsigned p = 0;
        if ((w >> (2 * b)) & 1) p |= 0x3F80u;          // bf16 1.0 in low half
        if ((w >> (2 * b + 1)) & 1) p |= 0x3F800000u;  // bf16 1.0 in high half
        out[b] = p;
    }
    uint4* dst = (uint4*)(g_Rb16 + (size_t)i * NN + t * 16);
    dst[0] = make_uint4(out[0], out[1], out[2], out[3]);
    dst[1] = make_uint4(out[4], out[5], out[6], out[7]);
}

// x prep: transpose+split -> xt_hi/lo, and row-major split -> xh/xl (one read of x)
__global__ void k_xprep(const float* __restrict__ x) {
    __shared__ float tile[32][33];
    int bf = blockIdx.x * 32, bn = blockIdx.y * 32;
    int tx = threadIdx.x, ty = threadIdx.y;  // (32, 8)
    for (int r = ty; r < 32; r += 8) {
        float v = x[(size_t)(bn + r) * DD + bf + tx];
        tile[r][tx] = v;
        __nv_bfloat16 h = __float2bfloat16(v);
        g_xh[(size_t)(bn + r) * DD + bf + tx] = h;
        g_xl[(size_t)(bn + r) * DD + bf + tx] = __float2bfloat16(v - __bfloat162float(h));
    }
    __syncthreads();
    for (int r = ty; r < 32; r += 8) {
        float v = tile[tx][r];  // x[bn+tx][bf+r]
        __nv_bfloat16 h = __float2bfloat16(v);
        g_xt_hi[(size_t)(bf + r) * NN + bn + tx] = h;
        g_xt_lo[(size_t)(bf + r) * NN + bn + tx] = __float2bfloat16(v - __bfloat162float(h));
    }
}

// transpose+split weight W[K][N] -> Wt[N][K] bf16 hi/lo
__global__ void k_wt(const float* __restrict__ W, int K, int N,
                     __nv_bfloat16* __restrict__ oh, __nv_bfloat16* __restrict__ ol) {
    __shared__ float tile[32][33];
    int bk = blockIdx.x * 32, bn = blockIdx.y * 32;
    int tx = threadIdx.x, ty = threadIdx.y;  // (32, 8)
    for (int r = ty; r < 32; r += 8)
        tile[r][tx] = W[(size_t)(bk + r) * N + bn + tx];
    __syncthreads();
    for (int r = ty; r < 32; r += 8) {
        float v = tile[tx][r];  // W[bk+tx][bn+r]
        __nv_bfloat16 h = __float2bfloat16(v);
        ol[(size_t)(bn + r) * K + bk + tx] = __float2bfloat16(v - __bfloat162float(h));
        oh[(size_t)(bn + r) * K + bk + tx] = h;
    }
}

// batched version for the 4 encoder weights (all 512x512)
struct WPtrs { const float* W[4]; };
__global__ void k_wt4(WPtrs wp, __nv_bfloat16* __restrict__ oh, __nv_bfloat16* __restrict__ ol) {
    __shared__ float tile[32][33];
    int z = blockIdx.z;
    const float* W = wp.W[z];
    __nv_bfloat16* ohz = oh + (size_t)z * DD * HHH;
    __nv_bfloat16* olz = ol + (size_t)z * DD * HHH;
    int bk = blockIdx.x * 32, bn = blockIdx.y * 32;
    int tx = threadIdx.x, ty = threadIdx.y;
    for (int r = ty; r < 32; r += 8)
        tile[r][tx] = W[(size_t)(bk + r) * HHH + bn + tx];
    __syncthreads();
    for (int r = ty; r < 32; r += 8) {
        float v = tile[tx][r];
        __nv_bfloat16 h = __float2bfloat16(v);
        olz[(size_t)(bn + r) * DD + bk + tx] = __float2bfloat16(v - __bfloat162float(h));
        ohz[(size_t)(bn + r) * DD + bk + tx] = h;
    }
}

// ---------------- tensor-core GEMMs ----------------
#define MMA_BF16(c, a, b) asm volatile( \
    "mma.sync.aligned.m16n8k16.row.col.f32.bf16.bf16.f32 " \
    "{%0,%1,%2,%3}, {%4,%5,%6,%7}, {%8,%9}, {%0,%1,%2,%3};" \
    : "+f"(c[0]), "+f"(c[1]), "+f"(c[2]), "+f"(c[3]) \
    : "r"(a[0]), "r"(a[1]), "r"(a[2]), "r"(a[3]), "r"(b[0]), "r"(b[1]))

// ego = (R @ (x_hi + x_lo)) * cinv,  R bf16 exact 0/1. CTA 128x128, KT=32.
// min 2 CTAs/SM: caps regs at 128, doubles latency-hiding warps.
__global__ __launch_bounds__(256, 2) void k_ego_mma(float* __restrict__ Cout) {
    extern __shared__ __nv_bfloat16 sm[];
    int tid = threadIdx.x;
    int lane = tid & 31, warp = tid >> 5;
    int wm = warp & 1, wn = warp >> 1;
    int br = blockIdx.x * 128, bc = blockIdx.y * 128;
    int g = lane >> 2, t4 = lane & 3;

    float acc[4][4][4];
#pragma unroll
    for (int mt = 0; mt < 4; mt++)
#pragma unroll
        for (int nt = 0; nt < 4; nt++)
#pragma unroll
            for (int q = 0; q < 4; q++) acc[mt][nt][q] = 0.f;

    auto copy_stage = [&](int s, int kb) {
        __nv_bfloat16* sb = sm + s * 3 * TSH;
#pragma unroll
        for (int c = 0; c < 2; c++) {
            int chunk = tid + c * 256;
            int row = chunk >> 2, seg = chunk & 3;
            int so = row * BSTRIDE + seg * 8;
            {
                unsigned da = (unsigned)__cvta_generic_to_shared(sb + so);
                const void* ga = g_Rb16 + (size_t)(br + row) * NN + kb + seg * 8;
                asm volatile("cp.async.ca.shared.global [%0], [%1], 16;" :: "r"(da), "l"(ga) : "memory");
            }
            {
                unsigned da = (unsigned)__cvta_generic_to_shared(sb + TSH + so);
                const void* ga = g_xt_hi + (size_t)(bc + row) * NN + kb + seg * 8;
                asm volatile("cp.async.ca.shared.global [%0], [%1], 16;" :: "r"(da), "l"(ga) : "memory");
            }
            {
                unsigned da = (unsigned)__cvta_generic_to_shared(sb + 2 * TSH + so);
                const void* ga = g_xt_lo + (size_t)(bc + row) * NN + kb + seg * 8;
                asm volatile("cp.async.ca.shared.global [%0], [%1], 16;" :: "r"(da), "l"(ga) : "memory");
            }
        }
        asm volatile("cp.async.commit_group;" ::: "memory");
    };

    const int KIT = NN / KT;
    copy_stage(0, 0);
    for (int kc = 0; kc < KIT; kc++) {
        if (kc + 1 < KIT) {
            copy_stage((kc + 1) & 1, (kc + 1) * KT);
            asm volatile("cp.async.wait_group 1;" ::: "memory");
        } else {
            asm volatile("cp.async.wait_group 0;" ::: "memory");
        }
        __syncthreads();
        const __nv_bfloat16* As = sm + (kc & 1) * 3 * TSH;
        const __nv_bfloat16* Bh = As + TSH;
        const __nv_bfloat16* Bl = Bh + TSH;
#pragma unroll
        for (int k0 = 0; k0 < KT; k0 += 16) {
            unsigned a[4][4], bh[4][2], bl[4][2];
#pragma unroll
            for (int mt = 0; mt < 4; mt++) {
                const __nv_bfloat16* p0 = As + (wm * 64 + mt * 16 + g) * BSTRIDE + k0 + 2 * t4;
                a[mt][0] = *(const unsigned*)p0;
                a[mt][1] = *(const unsigned*)(p0 + 8 * BSTRIDE);
                a[mt][2] = *(const unsigned*)(p0 + 8);
                a[mt][3] = *(const unsigned*)(p0 + 8 * BSTRIDE + 8);
            }
#pragma unroll
            for (int nt = 0; nt < 4; nt++) {
                const __nv_bfloat16* p0 = Bh + (wn * 32 + nt * 8 + g) * BSTRIDE + k0 + 2 * t4;
                bh[nt][0] = *(const unsigned*)p0;
                bh[nt][1] = *(const unsigned*)(p0 + 8);
                const __nv_bfloat16* p1 = Bl + (wn * 32 + nt * 8 + g) * BSTRIDE + k0 + 2 * t4;
                bl[nt][0] = *(const unsigned*)p1;
                bl[nt][1] = *(const unsigned*)(p1 + 8);
            }
#pragma unroll
            for (int mt = 0; mt < 4; mt++)
#pragma unroll
                for (int nt = 0; nt < 4; nt++) {
                    MMA_BF16(acc[mt][nt], a[mt], bh[nt]);
                    MMA_BF16(acc[mt][nt], a[mt], bl[nt]);
                }
        }
        __syncthreads();
    }

#pragma unroll
    for (int mt = 0; mt < 4; mt++) {
        int row0 = br + wm * 64 + mt * 16 + g;
        float i0 = g_cinv[row0];
        float i1 = g_cinv[row0 + 8];
#pragma unroll
        for (int nt = 0; nt < 4; nt++) {
            int col = bc + wn * 32 + nt * 8 + 2 * t4;
            float2 v0 = make_float2(acc[mt][nt][0] * i0, acc[mt][nt][1] * i0);
            float2 v1 = make_float2(acc[mt][nt][2] * i1, acc[mt][nt][3] * i1);
            *(float2*)&Cout[(size_t)row0 * DD + col] = v0;
            *(float2*)&Cout[(size_t)(row0 + 8) * DD + col] = v1;
        }
    }
}

// batched 4-way encoder GEMM: z selects feature. C = op(A_z @ B_z^T + s*bias_z),
// hi/lo 3-product split, output bf16 hi/lo into comb columns [z*HHH, z*HHH+HHH).
struct MmaB {
    const __nv_bfloat16 *Ah[4], *Al[4], *Bh[4], *Bl[4];
    const float* bias[4];
    const int* deg[4];
    int relu[4];
};
__global__ __launch_bounds__(256, 2) void k_mma4(MmaB P,
    __nv_bfloat16* __restrict__ Ch, __nv_bfloat16* __restrict__ Cl) {
    extern __shared__ __nv_bfloat16 sm[];
    const int SSZ = 512 * BSTRIDE;
    int z = blockIdx.z;
    const __nv_bfloat16* Ah = P.Ah[z];
    const __nv_bfloat16* Al = P.Al[z];
    const __nv_bfloat16* Bh = P.Bh[z];
    const __nv_bfloat16* Bl = P.Bl[z];
    const float* bias = P.bias[z];
    const int* deg = P.deg[z];
    int relu = P.relu[z];
    int tid = threadIdx.x;
    int lane = tid & 31, warp = tid >> 5;
    int wm = warp & 1, wn = warp >> 1;
    int br = blockIdx.x * 128, bc = blockIdx.y * 128;
    int g = lane >> 2, t4 = lane & 3;

    float acc[4][4][4];
#pragma unroll
    for (int mt = 0; mt < 4; mt++)
#pragma unroll
        for (int nt = 0; nt < 4; nt++)
#pragma unroll
            for (int q = 0; q < 4; q++) acc[mt][nt][q] = 0.f;

    auto copy_stage = [&](int s, int kb) {
        __nv_bfloat16* sb = sm + s * SSZ;
#pragma unroll
        for (int c = 0; c < 8; c++) {
            int chunk = tid + c * 256;
            int row = chunk >> 2, seg = chunk & 3;
            const __nv_bfloat16* gp;
            if (row < 128)      gp = Ah + (size_t)(br + row) * DD;
            else if (row < 256) gp = Al + (size_t)(br + row - 128) * DD;
            else if (row < 384) gp = Bh + (size_t)(bc + row - 256) * DD;
            else                gp = Bl + (size_t)(bc + row - 384) * DD;
            unsigned da = (unsigned)__cvta_generic_to_shared(sb + row * BSTRIDE + seg * 8);
            asm volatile("cp.async.ca.shared.global [%0], [%1], 16;"
                         :: "r"(da), "l"(gp + kb + seg * 8) : "memory");
        }
        asm volatile("cp.async.commit_group;" ::: "memory");
    };

    const int KIT = DD / KT;
    copy_stage(0, 0);
    for (int kc = 0; kc < KIT; kc++) {
        if (kc + 1 < KIT) {
            copy_stage((kc + 1) & 1, (kc + 1) * KT);
            asm volatile("cp.async.wait_group 1;" ::: "memory");
        } else {
            asm volatile("cp.async.wait_group 0;" ::: "memory");
        }
        __syncthreads();
        const __nv_bfloat16* sAh = sm + (kc & 1) * SSZ;
        const __nv_bfloat16* sAl = sAh + 128 * BSTRIDE;
        const __nv_bfloat16* sBh = sAl + 128 * BSTRIDE;
        const __nv_bfloat16* sBl = sBh + 128 * BSTRIDE;
#pragma unroll
        for (int k0 = 0; k0 < KT; k0 += 16) {
            unsigned ah[4][4], al[4][4], bh[4][2], bl[4][2];
#pragma unroll
            for (int mt = 0; mt < 4; mt++) {
                int ro = (wm * 64 + mt * 16 + g) * BSTRIDE + k0 + 2 * t4;
                ah[mt][0] = *(const unsigned*)(sAh + ro);
                ah[mt][1] = *(const unsigned*)(sAh + ro + 8 * BSTRIDE);
                ah[mt][2] = *(const unsigned*)(sAh + ro + 8);
                ah[mt][3] = *(const unsigned*)(sAh + ro + 8 * BSTRIDE + 8);
                al[mt][0] = *(const unsigned*)(sAl + ro);
                al[mt][1] = *(const unsigned*)(sAl + ro + 8 * BSTRIDE);
                al[mt][2] = *(const unsigned*)(sAl + ro + 8);
                al[mt][3] = *(const unsigned*)(sAl + ro + 8 * BSTRIDE + 8);
            }
#pragma unroll
            for (int nt = 0; nt < 4; nt++) {
                int ro = (wn * 32 + nt * 8 + g) * BSTRIDE + k0 + 2 * t4;
                bh[nt][0] = *(const unsigned*)(sBh + ro);
                bh[nt][1] = *(const unsigned*)(sBh + ro + 8);
                bl[nt][0] = *(const unsigned*)(sBl + ro);
                bl[nt][1] = *(const unsigned*)(sBl + ro + 8);
            }
#pragma unroll
            for (int mt = 0; mt < 4; mt++)
#pragma unroll
                for (int nt = 0; nt < 4; nt++) {
                    MMA_BF16(acc[mt][nt], ah[mt], bh[nt]);
                    MMA_BF16(acc[mt][nt], ah[mt], bl[nt]);
                    MMA_BF16(acc[mt][nt], al[mt], bh[nt]);
                }
        }
        __syncthreads();
    }

#pragma unroll
    for (int mt = 0; mt < 4; mt++) {
        int row0 = br + wm * 64 + mt * 16 + g;
        float s0 = deg ? (float)deg[row0] : 1.f;
        float s1 = deg ? (float)deg[row0 + 8] : 1.f;
#pragma unroll
        for (int nt = 0; nt < 4; nt++) {
            int col = bc + wn * 32 + nt * 8 + 2 * t4;
            float b0 = bias[col], b1 = bias[col + 1];
            float v00 = acc[mt][nt][0] + s0 * b0, v01 = acc[mt][nt][1] + s0 * b1;
            float v10 = acc[mt][nt][2] + s1 * b0, v11 = acc[mt][nt][3] + s1 * b1;
            if (relu) {
                v00 = fmaxf(v00, 0.f); v01 = fmaxf(v01, 0.f);
                v10 = fmaxf(v10, 0.f); v11 = fmaxf(v11, 0.f);
            }
            size_t o0 = (size_t)row0 * (4 * HHH) + z * HHH + col;
            size_t o1 = (size_t)(row0 + 8) * (4 * HHH) + z * HHH + col;
            __nv_bfloat162 h0, l0, h1, l1;
            h0.x = __float2bfloat16(v00); h0.y = __float2bfloat16(v01);
            l0.x = __float2bfloat16(v00 - __bfloat162float(h0.x));
            l0.y = __float2bfloat16(v01 - __bfloat162float(h0.y));
            h1.x = __float2bfloat16(v10); h1.y = __float2bfloat16(v11);
            l1.x = __float2bfloat16(v10 - __bfloat162float(h1.x));
            l1.y = __float2bfloat16(v11 - __bfloat162float(h1.y));
            *(__nv_bfloat162*)&Ch[o0] = h0;
            *(__nv_bfloat162*)&Cl[o0] = l0;
            *(__nv_bfloat162*)&Ch[o1] = h1;
            *(__nv_bfloat162*)&Cl[o1] = l1;
        }
    }
}

// fc GEMM (BN=64, fp32 out): logits = comb @ Wfc^T + b
__global__ __launch_bounds__(256, 2) void k_mma_fc(
    const __nv_bfloat16* __restrict__ Ah, const __nv_bfloat16* __restrict__ Al,
    const __nv_bfloat16* __restrict__ Bh, const __nv_bfloat16* __restrict__ Bl,
    const float* __restrict__ bias, float* __restrict__ Cf) {
    extern __shared__ __nv_bfloat16 sm[];
    const int K = 4 * HHH;
    const int SSZ = 384 * BSTRIDE;
    int tid = threadIdx.x;
    int lane = tid & 31, warp = tid >> 5;
    int wm = warp & 1, wn = warp >> 1;
    int br = blockIdx.x * 128, bc = 0;
    int g = lane >> 2, t4 = lane & 3;

    float acc[4][2][4];
#pragma unroll
    for (int mt = 0; mt < 4; mt++)
#pragma unroll
        for (int nt = 0; nt < 2; nt++)
#pragma unroll
            for (int q = 0; q < 4; q++) acc[mt][nt][q] = 0.f;

    auto copy_stage = [&](int s, int kb) {
        __nv_bfloat16* sb = sm + s * SSZ;
#pragma unroll
        for (int c = 0; c < 6; c++) {
            int chunk = tid + c * 256;
            int row = chunk >> 2, seg = chunk & 3;
            const __nv_bfloat16* gp;
            if (row < 128)      gp = Ah + (size_t)(br + row) * K;
            else if (row < 256) gp = Al + (size_t)(br + row - 128) * K;
            else if (row < 320) gp = Bh + (size_t)(bc + row - 256) * K;
            else                gp = Bl + (size_t)(bc + row - 320) * K;
            unsigned da = (unsigned)__cvta_generic_to_shared(sb + row * BSTRIDE + seg * 8);
            asm volatile("cp.async.ca.shared.global [%0], [%1], 16;"
                         :: "r"(da), "l"(gp + kb + seg * 8) : "memory");
        }
        asm volatile("cp.async.commit_group;" ::: "memory");
    };

    const int KIT = K / KT;
    copy_stage(0, 0);
    for (int kc = 0; kc < KIT; kc++) {
        if (kc + 1 < KIT) {
            copy_stage((kc + 1) & 1, (kc + 1) * KT);
            asm volatile("cp.async.wait_group 1;" ::: "memory");
        } else {
            asm volatile("cp.async.wait_group 0;" ::: "memory");
        }
        __syncthreads();
        const __nv_bfloat16* sAh = sm + (kc & 1) * SSZ;
        const __nv_bfloat16* sAl = sAh + 128 * BSTRIDE;
        const __nv_bfloat16* sBh = sAl + 128 * BSTRIDE;
        const __nv_bfloat16* sBl = sBh + 64 * BSTRIDE;
#pragma unroll
        for (int k0 = 0; k0 < KT; k0 += 16) {
            unsigned ah[4][4], al[4][4], bh[2][2], bl[2][2];
#pragma unroll
            for (int mt = 0; mt < 4; mt++) {
                int ro = (wm * 64 + mt * 16 + g) * BSTRIDE + k0 + 2 * t4;
                ah[mt][0] = *(const unsigned*)(sAh + ro);
                ah[mt][1] = *(const unsigned*)(sAh + ro + 8 * BSTRIDE);
                ah[mt][2] = *(const unsigned*)(sAh + ro + 8);
                ah[mt][3] = *(const unsigned*)(sAh + ro + 8 * BSTRIDE + 8);
                al[mt][0] = *(const unsigned*)(sAl + ro);
                al[mt][1] = *(const unsigned*)(sAl + ro + 8 * BSTRIDE);
                al[mt][2] = *(const unsigned*)(sAl + ro + 8);
                al[mt][3] = *(const unsigned*)(sAl + ro + 8 * BSTRIDE + 8);
            }
#pragma unroll
            for (int nt = 0; nt < 2; nt++) {
                int ro = (wn * 16 + nt * 8 + g) * BSTRIDE + k0 + 2 * t4;
                bh[nt][0] = *(const unsigned*)(sBh + ro);
                bh[nt][1] = *(const unsigned*)(sBh + ro + 8);
                bl[nt][0] = *(const unsigned*)(sBl + ro);
                bl[nt][1] = *(const unsigned*)(sBl + ro + 8);
            }
#pragma unroll
            for (int mt = 0; mt < 4; mt++)
#pragma unroll
                for (int nt = 0; nt < 2; nt++) {
                    MMA_BF16(acc[mt][nt], ah[mt], bh[nt]);
                    MMA_BF16(acc[mt][nt], ah[mt], bl[nt]);
                    MMA_BF16(acc[mt][nt], al[mt], bh[nt]);
                }
        }
        __syncthreads();
    }

#pragma unroll
    for (int mt = 0; mt < 4; mt++) {
        int row0 = br + wm * 64 + mt * 16 + g;
#pragma unroll
        for (int nt = 0; nt < 2; nt++) {
            int col = wn * 16 + nt * 8 + 2 * t4;
            float b0 = bias[col], b1 = bias[col + 1];
            *(float2*)&Cf[(size_t)row0 * OUTC + col] =
                make_float2(acc[mt][nt][0] + b0, acc[mt][nt][1] + b1);
            *(float2*)&Cf[(size_t)(row0 + 8) * OUTC + col] =
                make_float2(acc[mt][nt][2] + b0, acc[mt][nt][3] + b1);
        }
    }
}

// per-edge cosine similarity (float4 loads)
__global__ void k_cos_edge(const float* __restrict__ x) {
    int e = blockIdx.x * 8 + (threadIdx.x >> 5);
    int lane = threadIdx.x & 31;
    int s = g_src[e], d = g_dst[e];
    const float4* xs = (const float4*)(x + s * DD);
    const float4* xd = (const float4*)(x + d * DD);
    float acc = 0.f;
#pragma unroll
    for (int u = 0; u < 4; u++) {
        float4 a = xs[lane + 32 * u];
        float4 b = xd[lane + 32 * u];
        acc += a.x * b.x + a.y * b.y + a.z * b.z + a.w * b.w;
    }
    for (int o = 16; o > 0; o >>= 1) acc += __shfl_xor_sync(0xffffffffu, acc, o);
    if (lane == 0) g_cose[e] = acc * g_inv[s] * g_inv[d];
}

// fused: per-node softmax stats + cut & cosine feature accumulation (float4)
__global__ void k_cutcos(const float* __restrict__ x, const float* __restrict__ wgt) {
    int i = blockIdx.x, t = threadIdx.x;  // 128
    int beg = g_off_src[i];
    int deg = g_off_src[i + 1] - beg;
    __shared__ float red[128];
    float mx = -1e30f;
    for (int l = t; l < deg; l += 128) mx = fmaxf(mx, g_cose[g_csr_src[beg + l]]);
    red[t] = mx; __syncthreads();
    for (int d = 64; d > 0; d >>= 1) {
        if (t < d) red[t] = fmaxf(red[t], red[t + d]);
        __syncthreads();
    }
    float m = (deg > 0) ? red[0] : 0.f;
    __syncthreads();
    float sp = 0.f;
    for (int l = t; l < deg; l += 128) sp += expf(g_cose[g_csr_src[beg + l]] - m);
    red[t] = sp; __syncthreads();
    for (int d = 64; d > 0; d >>= 1) {
        if (t < d) red[t] += red[t + d];
        __syncthreads();
    }
    float den = red[0];
    float dsafe = (deg > 0 && den > 0.f) ? den : 1.f;
    __syncthreads();
    float wp = 0.f;
    for (int l = t; l < deg; l += 128) wp += wgt[g_csr_src[beg + l]];
    red[t] = wp; __syncthreads();
    for (int d = 64; d > 0; d >>= 1) {
        if (t < d) red[t] += red[t + d];
        __syncthreads();
    }
    float wsum = red[0];
    __syncthreads();
    __shared__ int sd[128];
    __shared__ float sw[128];
    __shared__ float sa[128];
    float4 ac = make_float4(0.f, 0.f, 0.f, 0.f);
    float4 as = make_float4(0.f, 0.f, 0.f, 0.f);
    float tot = 0.f;
    for (int base = 0; base < deg; base += 128) {
        int l = base + t;
        if (l < deg) {
            int e = g_csr_src[beg + l];
            sd[t] = g_dst[e];
            sw[t] = wgt[e];
            sa[t] = expf(g_cose[e] - m) / dsafe;
        }
        __syncthreads();
        int lim = min(128, deg - base);
        for (int u = 0; u < lim; u++) {
            float4 v = ((const float4*)(x + sd[u] * DD))[t];
            float w1 = sw[u], w2 = sa[u];
            tot += w2;
            ac.x += w1 * v.x; ac.y += w1 * v.y; ac.z += w1 * v.z; ac.w += w1 * v.w;
            as.x += w2 * v.x; as.y += w2 * v.y; as.z += w2 * v.z; as.w += w2 * v.w;
        }
        __syncthreads();
    }
    bool use = (deg > 0) && (wsum > 0.f);
    float invc = use ? 1.f / wsum : 0.f;
    float tsafe = (tot > 0.f) ? tot : 1.f;
    float4 xv = ((const float4*)(x + i * DD))[t];
    float4 oc, os;
    oc.x = use ? ac.x * invc : xv.x;  oc.y = use ? ac.y * invc : xv.y;
    oc.z = use ? ac.z * invc : xv.z;  oc.w = use ? ac.w * invc : xv.w;
    float it = 1.f / tsafe;
    os.x = (deg > 0) ? as.x * it : xv.x;  os.y = (deg > 0) ? as.y * it : xv.y;
    os.z = (deg > 0) ? as.z * it : xv.z;  os.w = (deg > 0) ? as.w * it : xv.w;
    ((float4*)(g_cut + i * DD))[t] = oc;
    ((float4*)(g_cosf + i * DD))[t] = os;
}

// fused aggregation over in-edges (float4 gathers); writes bf16 hi/lo splits
__global__ void k_agg3() {
    int i = blockIdx.x, t = threadIdx.x;  // 128, thread covers cols 4t..4t+3
    int beg = g_off_dst[i];
    int deg = g_off_dst[i + 1] - beg;
    __shared__ int ss[128];
    float4 aE = make_float4(0.f, 0.f, 0.f, 0.f);
    float4 aC = make_float4(0.f, 0.f, 0.f, 0.f);
    float4 aS = make_float4(0.f, 0.f, 0.f, 0.f);
    for (int base = 0; base < deg; base += 128) {
        int l = base + t;
        if (l < deg) ss[t] = g_src[g_csr_dst[beg + l]];
        __syncthreads();
        int lim = min(128, deg - base);
        for (int u = 0; u < lim; u++) {
            int b = ss[u] * DD;
            float4 vE = ((const float4*)(g_ego + b))[t];
            float4 vC = ((const float4*)(g_cut + b))[t];
            float4 vS = ((const float4*)(g_cosf + b))[t];
            aE.x += vE.x; aE.y += vE.y; aE.z += vE.z; aE.w += vE.w;
            aC.x += vC.x; aC.y += vC.y; aC.z += vC.z; aC.w += vC.w;
            aS.x += vS.x; aS.y += vS.y; aS.z += vS.z; aS.w += vS.w;
        }
        __syncthreads();
    }
    int col = i * DD + 4 * t;
    float vE[4] = {aE.x, aE.y, aE.z, aE.w};
    float vC[4] = {aC.x, aC.y, aC.z, aC.w};
    float vS[4] = {aS.x, aS.y, aS.z, aS.w};
#pragma unroll
    for (int c = 0; c < 4; c++) {
        __nv_bfloat16 h;
        h = __float2bfloat16(vE[c]);
        g_aggEh[col + c] = h; g_aggEl[col + c] = __float2bfloat16(vE[c] - __bfloat162float(h));
        h = __float2bfloat16(vC[c]);
        g_aggCh[col + c] = h; g_aggCl[col + c] = __float2bfloat16(vC[c] - __bfloat162float(h));
        h = __float2bfloat16(vS[c]);
        g_aggSh[col + c] = h; g_aggSl[col + c] = __float2bfloat16(vS[c] - __bfloat162float(h));
    }
}

// row-wise log_softmax over 64 logits; warp per row
__global__ void k_lsm(float* __restrict__ out) {
    int row = blockIdx.x * 4 + (threadIdx.x >> 5);
    int lane = threadIdx.x & 31;
    float v0 = g_logits[row * OUTC + lane];
    float v1 = g_logits[row * OUTC + 32 + lane];
    float m = fmaxf(v0, v1);
    for (int o = 16; o > 0; o >>= 1) m = fmaxf(m, __shfl_xor_sync(0xffffffffu, m, o));
    float s = expf(v0 - m) + expf(v1 - m);
    for (int o = 16; o > 0; o >>= 1) s += __shfl_xor_sync(0xffffffffu, s, o);
    float l = m + logf(s);
    out[row * OUTC + lane] = v0 - l;
    out[row * OUTC + 32 + lane] = v1 - l;
}

// ---------------- launcher ----------------
extern "C" void kernel_launch(void* const* d_in, const int* in_sizes, int n_in,
                              void* d_out, int out_size) {
    const float* x      = (const float*)d_in[0];
    const unsigned* raw = (const unsigned*)d_in[1];
    const float* ew     = (const float*)d_in[2];
    const float* W_ego  = (const float*)d_in[3];
    const float* b_ego  = (const float*)d_in[4];
    const float* W_cut  = (const float*)d_in[5];
    const float* b_cut  = (const float*)d_in[6];
    const float* W_cos  = (const float*)d_in[7];
    const float* b_cos  = (const float*)d_in[8];
    const float* W_glob = (const float*)d_in[9];
    const float* b_glob = (const float*)d_in[10];
    const float* W_fc   = (const float*)d_in[11];
    const float* b_fc   = (const float*)d_in[12];
    float* out = (float*)d_out;

    float *p_logits, *p_ego;
    int *p_degdst;
    cudaGetSymbolAddress((void**)&p_logits, g_logits);
    cudaGetSymbolAddress((void**)&p_ego, g_ego);
    cudaGetSymbolAddress((void**)&p_degdst, g_deg_dst);
    __nv_bfloat16 *p_aEh, *p_aEl, *p_aCh, *p_aCl, *p_aSh, *p_aSl;
    __nv_bfloat16 *p_xh, *p_xl, *p_ch, *p_cl, *p_Wth, *p_Wtl;
    cudaGetSymbolAddress((void**)&p_aEh, g_aggEh);
    cudaGetSymbolAddress((void**)&p_aEl, g_aggEl);
    cudaGetSymbolAddress((void**)&p_aCh, g_aggCh);
    cudaGetSymbolAddress((void**)&p_aCl, g_aggCl);
    cudaGetSymbolAddress((void**)&p_aSh, g_aggSh);
    cudaGetSymbolAddress((void**)&p_aSl, g_aggSl);
    cudaGetSymbolAddress((void**)&p_xh, g_xh);
    cudaGetSymbolAddress((void**)&p_xl, g_xl);
    cudaGetSymbolAddress((void**)&p_ch, g_combh);
    cudaGetSymbolAddress((void**)&p_cl, g_combl);
    cudaGetSymbolAddress((void**)&p_Wth, g_Wth);
    cudaGetSymbolAddress((void**)&p_Wtl, g_Wtl);

    static const size_t EGO_SMEM = 2 * 3 * TSH * sizeof(__nv_bfloat16);            // 61440
    static const size_t MMA4_SMEM = 2 * 512 * BSTRIDE * sizeof(__nv_bfloat16);     // 81920
    static const size_t FC_SMEM  = 2 * 384 * BSTRIDE * sizeof(__nv_bfloat16);      // 61440
    cudaFuncSetAttribute(k_ego_mma, cudaFuncAttributeMaxDynamicSharedMemorySize, (int)EGO_SMEM);
    cudaFuncSetAttribute(k_mma4, cudaFuncAttributeMaxDynamicSharedMemorySize, (int)MMA4_SMEM);
    cudaFuncSetAttribute(k_mma_fc, cudaFuncAttributeMaxDynamicSharedMemorySize, (int)FC_SMEM);

    // worker streams + fork/join events, created once (outside graph capture)
    static cudaStream_t s1 = 0, s2 = 0;
    static cudaEvent_t evRoot = 0, evEdge = 0, evXprep = 0, evWt = 0, evCut = 0;
    if (!s1) {
        cudaStreamCreateWithFlags(&s1, cudaStreamNonBlocking);
        cudaStreamCreateWithFlags(&s2, cudaStreamNonBlocking);
        cudaEventCreateWithFlags(&evRoot, cudaEventDisableTiming);
        cudaEventCreateWithFlags(&evEdge, cudaEventDisableTiming);
        cudaEventCreateWithFlags(&evXprep, cudaEventDisableTiming);
        cudaEventCreateWithFlags(&evWt, cudaEventDisableTiming);
        cudaEventCreateWithFlags(&evCut, cudaEventDisableTiming);
    }

    // fork
    cudaEventRecord(evRoot, 0);
    cudaStreamWaitEvent(s1, evRoot, 0);
    cudaStreamWaitEvent(s2, evRoot, 0);

    // --- s1: input-only prep (x splits + weight transposes) ---
    k_xprep<<<dim3(DD / 32, NN / 32), dim3(32, 8), 0, s1>>>(x);
    cudaEventRecord(evXprep, s1);
    {
        WPtrs wp; wp.W[0] = W_ego; wp.W[1] = W_cut; wp.W[2] = W_cos; wp.W[3] = W_glob;
        k_wt4<<<dim3(DD / 32, HHH / 32, 4), dim3(32, 8), 0, s1>>>(wp, p_Wth, p_Wtl);
    }
    k_wt<<<dim3(4 * HHH / 32, OUTC / 32), dim3(32, 8), 0, s1>>>(
        W_fc, 4 * HHH, OUTC, p_Wth + WT_FC_OFF, p_Wtl + WT_FC_OFF);
    cudaEventRecord(evWt, s1);

    // --- s2: norm (x-only), then CSR + cosine path after edges land ---
    k_norm<<<NN, 128, 0, s2>>>(x);

    // --- s0: graph build ---
    k_zero<<<512, 1024>>>();
    k_convert<<<EE / 256, 256>>>(raw);
    k_edge<<<EE / 256, 256>>>();
    cudaEventRecord(evEdge, 0);

    // s2 continues: scans, fill, cosine/cut features
    cudaStreamWaitEvent(s2, evEdge, 0);
    k_scan2<<<2, 1024, 0, s2>>>();
    k_fill<<<EE / 256, 256, 0, s2>>>();
    k_cos_edge<<<EE / 8, 256, 0, s2>>>(x);
    k_cutcos<<<NN, 128, 0, s2>>>(x, ew);
    cudaEventRecord(evCut, s2);

    // s0 continues: ego path
    k_rbits<<<NN, 128>>>();
    k_expandR<<<NN, 256>>>();
    cudaStreamWaitEvent(0, evXprep, 0);
    k_ego_mma<<<dim3(NN / 128, DD / 128), 256, EGO_SMEM>>>(p_ego);

    // join: aggregation + GEMMs + epilogue on s0
    cudaStreamWaitEvent(0, evCut, 0);
    k_agg3<<<NN, 128>>>();
    cudaStreamWaitEvent(0, evWt, 0);
    {
        MmaB P;
        P.Ah[0] = p_aEh; P.Al[0] = p_aEl;
        P.Ah[1] = p_aCh; P.Al[1] = p_aCl;
        P.Ah[2] = p_aSh; P.Al[2] = p_aSl;
        P.Ah[3] = p_xh;  P.Al[3] = p_xl;
        for (int z = 0; z < 4; z++) {
            P.Bh[z] = p_Wth + (size_t)z * DD * HHH;
            P.Bl[z] = p_Wtl + (size_t)z * DD * HHH;
        }
        P.bias[0] = b_ego; P.bias[1] = b_cut; P.bias[2] = b_cos; P.bias[3] = b_glob;
        P.deg[0] = p_degdst; P.deg[1] = p_degdst; P.deg[2] = p_degdst; P.deg[3] = (const int*)0;
        P.relu[0] = 1; P.relu[1] = 1; P.relu[2] = 1; P.relu[3] = 0;
        k_mma4<<<dim3(NN / 128, HHH / 128, 4), 256, MMA4_SMEM>>>(P, p_ch, p_cl);
    }
    k_mma_fc<<<NN / 128, 256, FC_SMEM>>>(p_ch, p_cl, p_Wth + WT_FC_OFF, p_Wtl + WT_FC_OFF,
                                         b_fc, p_logits);
    k_lsm<<<NN / 4, 128>>>(out);

    (void)in_sizes; (void)n_in; (void)out_size;
}